// round 3
// baseline (speedup 1.0000x reference)
#include <cuda_runtime.h>
#include <cstdint>
#include <cstddef>

#define LOG2E 1.4426950408889634f
#define LN2f  0.6931471805599453f
#define NEGV  -100.0f

#define T_LEN 1024
#define V_N   8000
#define WSZ   8
#define NW    (T_LEN / WSZ)
#define TPB   64          // threads per block = sequences per block
#define GRID  128         // 128 * 64 = 8192 sequences

// -------- device scratch (static allocation only) ---------------------------
__device__ __align__(16) float4 g_Bt4[V_N];  // emission PROBS * 2^13, [y].{s0..s3}
__device__ float g_par[16];  // [0..3] pi_log2, [4..7] pi_prob, [8..11] A0p, [12..15] A1p

// ---------------------------- prep kernel -----------------------------------
// Replicates reference _log_params in fp32, converts to scaled probability domain.
__global__ void prep_kernel(const float* __restrict__ init_pi,
                            const float* __restrict__ init_A,
                            const float* __restrict__ init_B) {
    __shared__ float red[256];
    int tid = threadIdx.x;
    int s = blockIdx.x;
    if (s < 4) {
        const float* row = init_B + (size_t)s * V_N;
        float mx = -1e30f;
        for (int i = tid; i < V_N; i += 256) mx = fmaxf(mx, row[i]);
        red[tid] = mx; __syncthreads();
        for (int o = 128; o; o >>= 1) {
            if (tid < o) red[tid] = fmaxf(red[tid], red[tid + o]);
            __syncthreads();
        }
        mx = red[0]; __syncthreads();
        float sm = 0.f;
        for (int i = tid; i < V_N; i += 256) sm += expf(row[i] - mx);
        red[tid] = sm; __syncthreads();
        for (int o = 128; o; o >>= 1) {
            if (tid < o) red[tid] += red[tid + o];
            __syncthreads();
        }
        float lse = mx + logf(red[0]);
        for (int i = tid; i < V_N; i += 256) {
            float lb2 = fmaxf(row[i] - lse, NEGV) * LOG2E;   // log2 emission
            ((float*)&g_Bt4[i])[s] = exp2f(lb2 + 13.0f);     // scaled prob
        }
    } else if (tid == 0) {
        // pi: mask [0,-100,-100,0], log_softmax axis 0, clamp -100
        float x[4];
        const float pim[4] = {0.f, NEGV, NEGV, 0.f};
        float mx = -1e30f;
        for (int i = 0; i < 4; ++i) { x[i] = init_pi[i] + pim[i]; mx = fmaxf(mx, x[i]); }
        float smv = 0.f;
        for (int i = 0; i < 4; ++i) smv += expf(x[i] - mx);
        float lse = mx + logf(smv);
        float plog2[4];
        for (int i = 0; i < 4; ++i) {
            plog2[i] = fmaxf(x[i] - lse, NEGV) * LOG2E;
            g_par[i] = plog2[i];
            g_par[4 + i] = exp2f(plog2[i]);
        }
        // A: pattern mask, row log_softmax, clamp, -> probs
        const int pat[16] = {0,1,1,0, 0,1,1,0, 1,0,0,1, 1,0,0,1};
        float Ap[16];
        for (int r = 0; r < 4; ++r) {
            float y[4]; float m2 = -1e30f;
            for (int j = 0; j < 4; ++j) {
                y[j] = init_A[r * 4 + j] + (pat[r * 4 + j] ? 0.f : NEGV);
                m2 = fmaxf(m2, y[j]);
            }
            float s2 = 0.f;
            for (int j = 0; j < 4; ++j) s2 += expf(y[j] - m2);
            float l2 = m2 + logf(s2);
            for (int j = 0; j < 4; ++j)
                Ap[r * 4 + j] = expf(fmaxf(y[j] - l2, NEGV));
        }
        // allowed preds: s0<-{2,3}, s1<-{0,1}, s2<-{0,1}, s3<-{2,3}
        g_par[8]  = Ap[2*4+0]; g_par[12] = Ap[3*4+0];   // s0
        g_par[9]  = Ap[0*4+1]; g_par[13] = Ap[1*4+1];   // s1
        g_par[10] = Ap[0*4+2]; g_par[14] = Ap[1*4+2];   // s2
        g_par[11] = Ap[2*4+3]; g_par[15] = Ap[3*4+3];   // s3
    }
}

// ---------------------------- main kernel -----------------------------------
__device__ __forceinline__ float flg2(float x) {
    float r; asm("lg2.approx.ftz.f32 %0, %1;" : "=f"(r) : "f"(x)); return r;
}

__global__ void __launch_bounds__(TPB, 1)
hmm_kernel(const int* __restrict__ Y, const float* __restrict__ mask,
           float* __restrict__ out) {
    extern __shared__ float4 bt[];            // 8000 * 16B = 128 KB

    // stage scaled-prob emission table (LDG.128 -> STS.128, independent, MLP)
    for (int i = threadIdx.x; i < V_N; i += TPB) bt[i] = g_Bt4[i];
    __syncthreads();

    const int seq = blockIdx.x * TPB + threadIdx.x;
    const int4*   yrow4 = (const int4*)(Y + (size_t)seq * T_LEN);
    const float4* mrow4 = (const float4*)(mask + (size_t)seq * T_LEN);

    const float pl0 = g_par[0],  pl1 = g_par[1],  pl2 = g_par[2],  pl3 = g_par[3];
    const float pp0 = g_par[4],  pp1 = g_par[5],  pp2 = g_par[6],  pp3 = g_par[7];
    const float A00 = g_par[8],  A01 = g_par[9],  A02 = g_par[10], A03 = g_par[11];
    const float A10 = g_par[12], A11 = g_par[13], A12 = g_par[14], A13 = g_par[15];

    float* o0 = out + (size_t)(seq * 4 + 0) * T_LEN;
    float* o1 = out + (size_t)(seq * 4 + 1) * T_LEN;
    float* o2 = out + (size_t)(seq * 4 + 2) * T_LEN;
    float* o3 = out + (size_t)(seq * 4 + 3) * T_LEN;

    // 3-window Y/mask register pipeline (cur, +1, +2), each window = 2 int4 / 2 float4
    int4   yc0, yc1, yn10, yn11, yn20, yn21;
    float4 mc0, mc1, mn10, mn11, mn20, mn21;
    yc0  = yrow4[0]; yc1  = yrow4[1];
    yn10 = yrow4[2]; yn11 = yrow4[3];
    yn20 = yrow4[4]; yn21 = yrow4[5];
    mc0  = mrow4[0]; mc1  = mrow4[1];
    mn10 = mrow4[2]; mn11 = mrow4[3];
    mn20 = mrow4[4]; mn21 = mrow4[5];

    float a0, a1, a2, a3;       // state probs (scaled)
    int   Cint = 0;             // exact log2 scale accumulator
    float b0[WSZ], b1[WSZ], b2[WSZ], b3[WSZ];

    float4 e = bt[yc0.x];       // emission for t = 0

    for (int w = 0; w < NW; ++w) {
        if (w > 0) {
            // rotate pipeline; prefetch window w+2 (guarded, uniform branch)
            yc0 = yn10; yc1 = yn11; mc0 = mn10; mc1 = mn11;
            yn10 = yn20; yn11 = yn21; mn10 = mn20; mn11 = mn21;
            if (w + 2 < NW) {
                yn20 = yrow4[(w + 2) * 2];     yn21 = yrow4[(w + 2) * 2 + 1];
                mn20 = mrow4[(w + 2) * 2];     mn21 = mrow4[(w + 2) * 2 + 1];
            }
        }
        const int   y8[8] = {yc0.x, yc0.y, yc0.z, yc0.w, yc1.x, yc1.y, yc1.z, yc1.w};
        const float m8[8] = {mc0.x, mc0.y, mc0.z, mc0.w, mc1.x, mc1.y, mc1.z, mc1.w};
        const int   ynextw = yn10.x;   // first y of window w+1 (stale-but-valid at w=NW-1)

#pragma unroll
        for (int j = 0; j < WSZ; ++j) {
            float4 ec = e;
            int ynx = (j < 7) ? y8[j + 1] : ynextw;
            e = bt[ynx];                                   // prefetch next step (off-chain)

            if (j == 0 && w == 0) {
                // t = 0: exact log-domain init (handles -100 pi states)
                a0 = pp0 * ec.x;  a1 = pp1 * ec.y;
                a2 = pp2 * ec.z;  a3 = pp3 * ec.w;
                b0[0] = (pl0 + flg2(ec.x) - 13.0f) * LN2f;
                b1[0] = (pl1 + flg2(ec.y) - 13.0f) * LN2f;
                b2[0] = (pl2 + flg2(ec.z) - 13.0f) * LN2f;
                b3[0] = (pl3 + flg2(ec.w) - 13.0f) * LN2f;
                Cint = -13;
            } else {
                float mk = m8[j];
                // chain: FMUL -> FFMA -> FMUL -> SEL (4 states in parallel ILP)
                float n0 = fmaf(a3, A10, a2 * A00);
                float n1 = fmaf(a1, A11, a0 * A01);
                float n2 = fmaf(a1, A12, a0 * A02);
                float n3 = fmaf(a3, A13, a2 * A03);
                n0 *= ec.x;  n1 *= ec.y;  n2 *= ec.z;  n3 *= ec.w;
                bool sel = (mk > 0.5f);
                // masked step: keep old log value; compensate the -13 scale shift
                a0 = sel ? n0 : a0 * 8192.0f;
                a1 = sel ? n1 : a1 * 8192.0f;
                a2 = sel ? n2 : a2 * 8192.0f;
                a3 = sel ? n3 : a3 * 8192.0f;
                Cint -= 13;
                float Cf = (float)Cint * LN2f;             // exact int -> float
                b0[j] = fmaf(flg2(a0), LN2f, Cf);          // off-chain MUFU
                b1[j] = fmaf(flg2(a1), LN2f, Cf);
                b2[j] = fmaf(flg2(a2), LN2f, Cf);
                b3[j] = fmaf(flg2(a3), LN2f, Cf);
            }
        }

        // flush 8 columns per state row: two float4 = one full 32B sector each
        int toff = w * WSZ;
        *(float4*)(o0 + toff)     = make_float4(b0[0], b0[1], b0[2], b0[3]);
        *(float4*)(o0 + toff + 4) = make_float4(b0[4], b0[5], b0[6], b0[7]);
        *(float4*)(o1 + toff)     = make_float4(b1[0], b1[1], b1[2], b1[3]);
        *(float4*)(o1 + toff + 4) = make_float4(b1[4], b1[5], b1[6], b1[7]);
        *(float4*)(o2 + toff)     = make_float4(b2[0], b2[1], b2[2], b2[3]);
        *(float4*)(o2 + toff + 4) = make_float4(b2[4], b2[5], b2[6], b2[7]);
        *(float4*)(o3 + toff)     = make_float4(b3[0], b3[1], b3[2], b3[3]);
        *(float4*)(o3 + toff + 4) = make_float4(b3[4], b3[5], b3[6], b3[7]);

        // rescale: recenter max state exponent at 2^0 (exact integer bookkeeping)
        unsigned bb = __float_as_uint(a0);
        bb = max(bb, __float_as_uint(a1));
        bb = max(bb, __float_as_uint(a2));
        bb = max(bb, __float_as_uint(a3));
        int Ex = (int)(bb >> 23) - 127;
        float sc = __uint_as_float((unsigned)(127 - Ex) << 23);   // 2^-Ex
        a0 *= sc; a1 *= sc; a2 *= sc; a3 *= sc;
        Cint += Ex;
    }
}

// ---------------------------- launch ----------------------------------------
extern "C" void kernel_launch(void* const* d_in, const int* in_sizes, int n_in,
                              void* d_out, int out_size) {
    const int*   Y    = (const int*)d_in[0];
    const float* mask = (const float*)d_in[1];
    const float* pi   = (const float*)d_in[2];
    const float* A    = (const float*)d_in[3];
    const float* B    = (const float*)d_in[4];
    float* out = (float*)d_out;

    cudaFuncSetAttribute(hmm_kernel,
                         cudaFuncAttributeMaxDynamicSharedMemorySize,
                         V_N * (int)sizeof(float4));

    prep_kernel<<<5, 256>>>(pi, A, B);
    hmm_kernel<<<GRID, TPB, V_N * sizeof(float4)>>>(Y, mask, out);
}